// round 5
// baseline (speedup 1.0000x reference)
#include <cuda_runtime.h>
#include <math_constants.h>

// Fixed problem shape: x[B=4, C=256, H=200, W=320] float32 -> out[B, H, W] float32
#define Bn 4
#define Cn 256
#define Hn 200
#define Wn 320
#define HWn (Hn * Wn)            // 64000
#define CHWn (Cn * HWn)          // 16384000
#define HW4 (HWn / 4)            // 16000 float4 groups per channel plane
#define NPIX (Bn * HWn)          // 256000 pixels
#define NGRP (Bn * HW4)          // 64000 float4 pixel groups

#define CHUNKS 4                 // channel chunks
#define CPC   (Cn / CHUNKS)      // 64 channels per chunk

#define NEG_INF (-CUDART_INF_F)

// Scratch: per (chunk, pixel) partial max and packed (argmax | count<<16).
__device__ float4 g_pmax[CHUNKS * NGRP];   // 4 MB
__device__ int4   g_pmeta[CHUNKS * NGRP];  // 4 MB

// ---------------- Kernel A: channel-chunk partial depth-wise argmax ----------
__global__ void __launch_bounds__(256)
phaseA_kernel(const float* __restrict__ x) {
    const int t = blockIdx.x * 256 + threadIdx.x;   // 0..CHUNKS*NGRP-1 exact
    const int chunk = t / NGRP;
    const int gg    = t - chunk * NGRP;             // global float4 group
    const int b     = gg / HW4;
    const int pg    = gg - b * HW4;                 // group within plane

    const float4* __restrict__ src =
        reinterpret_cast<const float4*>(x + (size_t)b * CHWn
                                          + (size_t)chunk * CPC * HWn) + pg;

    float mx[4]; int am[4]; int cn[4];
#pragma unroll
    for (int k = 0; k < 4; ++k) { mx[k] = NEG_INF; am[k] = 0; cn[k] = 0; }

#pragma unroll 2
    for (int c0 = 0; c0 < CPC; c0 += 8) {
        float4 v[8];
#pragma unroll
        for (int j = 0; j < 8; ++j)
            v[j] = __ldg(src + (size_t)(c0 + j) * HW4);
#pragma unroll
        for (int j = 0; j < 8; ++j) {
            const float vv[4] = {v[j].x, v[j].y, v[j].z, v[j].w};
#pragma unroll
            for (int k = 0; k < 4; ++k) {
                const bool gt = vv[k] > mx[k];
                const bool eq = vv[k] == mx[k];
                cn[k] = gt ? 1 : (cn[k] + (eq ? 1 : 0));
                am[k] = gt ? (c0 + j) : am[k];
                mx[k] = fmaxf(mx[k], vv[k]);
            }
        }
    }

    g_pmax[t] = make_float4(mx[0], mx[1], mx[2], mx[3]);
    int4 meta;
    meta.x = (chunk * CPC + am[0]) | (cn[0] << 16);
    meta.y = (chunk * CPC + am[1]) | (cn[1] << 16);
    meta.z = (chunk * CPC + am[2]) | (cn[2] << 16);
    meta.w = (chunk * CPC + am[3]) | (cn[3] << 16);
    g_pmeta[t] = meta;
}

// Max over the 9x9 window (clipped at borders) of one channel plane.
// Fixed 9 row iterations (rows clamped; duplicates harmless under max) so the
// loop fully unrolls; 27 independent LDG.128 get front-batched.
__device__ __forceinline__ float window_max(const float* __restrict__ chan,
                                            int h, int w) {
    const int lo = w - 4;
    const int hi = w + 4;
    int wa = (w - 4) & ~3;
    if (wa < 0) wa = 0;
    if (wa > Wn - 12) wa = Wn - 12;   // 308, stays 16B-aligned

    float nb = NEG_INF;
#pragma unroll
    for (int i = 0; i < 9; ++i) {
        const int r = min(max(h - 4 + i, 0), Hn - 1);
        const float4* p = reinterpret_cast<const float4*>(chan + r * Wn + wa);
        float4 a = __ldg(p + 0);
        float4 b = __ldg(p + 1);
        float4 c = __ldg(p + 2);
        float v[12] = {a.x, a.y, a.z, a.w, b.x, b.y, b.z, b.w, c.x, c.y, c.z, c.w};
#pragma unroll
        for (int j = 0; j < 12; ++j) {
            const int col = wa + j;
            const bool ok = (col >= lo) && (col <= hi);
            nb = fmaxf(nb, ok ? v[j] : NEG_INF);
        }
    }
    return nb;
}

// ---------------- Kernel B: merge partials + 9x9 local-max test --------------
__global__ void __launch_bounds__(256)
phaseB_kernel(const float* __restrict__ x, float* __restrict__ out) {
    const int p = blockIdx.x * 256 + threadIdx.x;   // 0..NPIX-1 exact
    const int b = p / HWn;
    const int r = p - b * HWn;
    const int h = r / Wn;
    const int w = r - h * Wn;

    const float* __restrict__ pmax  = reinterpret_cast<const float*>(g_pmax);
    const int*   __restrict__ pmeta = reinterpret_cast<const int*>(g_pmeta);

    // Merge the CHUNKS partials (branchless).
    float mx = NEG_INF; int am = 0; int cn = 0;
#pragma unroll
    for (int ch = 0; ch < CHUNKS; ++ch) {
        const float m    = pmax[ch * NPIX + p];
        const int   meta = pmeta[ch * NPIX + p];
        const bool gt = m > mx;
        const bool eq = m == mx;
        cn = gt ? (meta >> 16) : (cn + (eq ? (meta >> 16) : 0));
        am = gt ? (meta & 0xFFFF) : am;
        mx = fmaxf(mx, m);
    }

    const float* __restrict__ xb = x + (size_t)b * CHWn;
    float res;
    if (cn == 1) {
        const float* chan = xb + (size_t)am * HWn;
        const float nb = window_max(chan, h, w);
        res = (nb <= mx) ? mx : 0.0f;   // nb >= mx always (center included)
    } else {
        // Exact tie path (statistically ~0 pixels): every channel equal to the
        // max contributes mx if it is also its own 9x9 local max.
        const float* xp = xb + h * Wn + w;
        int cnt = 0;
        for (int c = 0; c < Cn; ++c) {
            const float v = __ldg(xp + (size_t)c * HWn);
            if (v == mx) {
                const float* chan = xb + (size_t)c * HWn;
                if (window_max(chan, h, w) <= mx) cnt++;
            }
        }
        res = mx * (float)cnt;
    }

    out[p] = res;
}

extern "C" void kernel_launch(void* const* d_in, const int* in_sizes, int n_in,
                              void* d_out, int out_size) {
    const float* x = (const float*)d_in[0];
    float* out = (float*)d_out;
    (void)in_sizes; (void)n_in; (void)out_size;

    phaseA_kernel<<<(CHUNKS * NGRP) / 256, 256>>>(x);        // 1000 blocks
    phaseB_kernel<<<NPIX / 256, 256>>>(x, out);              // 1000 blocks
}

// round 6
// speedup vs baseline: 1.0078x; 1.0078x over previous
#include <cuda_runtime.h>
#include <math_constants.h>

// Fixed problem shape: x[B=4, C=256, H=200, W=320] float32 -> out[B, H, W] float32
#define Bn 4
#define Cn 256
#define Hn 200
#define Wn 320
#define HWn (Hn * Wn)            // 64000
#define CHWn (Cn * HWn)          // 16384000
#define HW4 (HWn / 4)            // 16000 float4 groups per channel plane
#define NPIX (Bn * HWn)          // 256000 pixels
#define NGRP (Bn * HW4)          // 64000 float4 pixel groups

#define CHUNKS 4                 // channel chunks == lanes per pixel in phase B
#define CPC   (Cn / CHUNKS)      // 64 channels per chunk

#define NEG_INF (-CUDART_INF_F)

// Scratch: per (chunk, pixel) partial max and packed (argmax | count<<16).
__device__ float4 g_pmax[CHUNKS * NGRP];   // 4 MB
__device__ int4   g_pmeta[CHUNKS * NGRP];  // 4 MB

// ---------------- Kernel A: channel-chunk partial depth-wise argmax ----------
__global__ void __launch_bounds__(256)
phaseA_kernel(const float* __restrict__ x) {
    const int t = blockIdx.x * 256 + threadIdx.x;   // 0..CHUNKS*NGRP-1 exact
    const int chunk = t / NGRP;
    const int gg    = t - chunk * NGRP;             // global float4 group
    const int b     = gg / HW4;
    const int pg    = gg - b * HW4;                 // group within plane

    const float4* __restrict__ src =
        reinterpret_cast<const float4*>(x + (size_t)b * CHWn
                                          + (size_t)chunk * CPC * HWn) + pg;

    float mx[4]; int am[4]; int cn[4];
#pragma unroll
    for (int k = 0; k < 4; ++k) { mx[k] = NEG_INF; am[k] = 0; cn[k] = 0; }

#pragma unroll 2
    for (int c0 = 0; c0 < CPC; c0 += 8) {
        float4 v[8];
#pragma unroll
        for (int j = 0; j < 8; ++j)
            v[j] = __ldg(src + (size_t)(c0 + j) * HW4);
#pragma unroll
        for (int j = 0; j < 8; ++j) {
            const float vv[4] = {v[j].x, v[j].y, v[j].z, v[j].w};
#pragma unroll
            for (int k = 0; k < 4; ++k) {
                const bool gt = vv[k] > mx[k];
                const bool eq = vv[k] == mx[k];
                cn[k] = gt ? 1 : (cn[k] + (eq ? 1 : 0));
                am[k] = gt ? (c0 + j) : am[k];
                mx[k] = fmaxf(mx[k], vv[k]);
            }
        }
    }

    g_pmax[t] = make_float4(mx[0], mx[1], mx[2], mx[3]);
    int4 meta;
    meta.x = (chunk * CPC + am[0]) | (cn[0] << 16);
    meta.y = (chunk * CPC + am[1]) | (cn[1] << 16);
    meta.z = (chunk * CPC + am[2]) | (cn[2] << 16);
    meta.w = (chunk * CPC + am[3]) | (cn[3] << 16);
    g_pmeta[t] = meta;
}

// Max of one window row: 3 aligned float4 covering [wa, wa+12), masked to [lo,hi].
__device__ __forceinline__ float wrow_max(const float* __restrict__ chan,
                                          int r, int wa, int lo, int hi) {
    const float4* p = reinterpret_cast<const float4*>(chan + r * Wn + wa);
    float4 a = __ldg(p + 0);
    float4 b = __ldg(p + 1);
    float4 c = __ldg(p + 2);
    float v[12] = {a.x, a.y, a.z, a.w, b.x, b.y, b.z, b.w, c.x, c.y, c.z, c.w};
    float nb = NEG_INF;
#pragma unroll
    for (int j = 0; j < 12; ++j) {
        const int col = wa + j;
        const bool ok = (col >= lo) && (col <= hi);
        nb = fmaxf(nb, ok ? v[j] : NEG_INF);
    }
    return nb;
}

// ---------------- Kernel B: 4 lanes per pixel: merge + 9x9 local-max ---------
__global__ void __launch_bounds__(256)
phaseB_kernel(const float* __restrict__ x, float* __restrict__ out) {
    const int t = blockIdx.x * 256 + threadIdx.x;   // 0..4*NPIX-1 exact
    const int p = t >> 2;                           // pixel
    const int k = t & 3;                            // lane within nibble

    const int b  = p / HWn;
    const int rm = p - b * HWn;
    const int h  = rm / Wn;
    const int w  = rm - h * Wn;

    const float* __restrict__ pmax  = reinterpret_cast<const float*>(g_pmax);
    const int*   __restrict__ pmeta = reinterpret_cast<const int*>(g_pmeta);

    // Lane k owns chunk k's partial; nibble shfl-reduce (max, argmax, count).
    float m   = pmax[k * NPIX + p];
    int   meta = pmeta[k * NPIX + p];
#pragma unroll
    for (int s = 1; s < 4; s <<= 1) {
        const float om    = __shfl_xor_sync(0xFFFFFFFFu, m, s);
        const int   ometa = __shfl_xor_sync(0xFFFFFFFFu, meta, s);
        const bool gt = om > m;
        const bool eq = om == m;
        int cn = meta >> 16, am = meta & 0xFFFF;
        const int ocn = ometa >> 16, oam = ometa & 0xFFFF;
        cn = gt ? ocn : (cn + (eq ? ocn : 0));
        am = gt ? oam : am;
        m  = fmaxf(m, om);
        meta = am | (cn << 16);
    }
    const float mx = m;
    const int   am = meta & 0xFFFF;
    const int   cn = meta >> 16;

    // Window geometry (shared by all lanes of the pixel).
    const int lo = w - 4;
    const int hi = w + 4;
    int wa = (w - 4) & ~3;
    if (wa < 0) wa = 0;
    if (wa > Wn - 12) wa = Wn - 12;   // 308, stays 16B-aligned

    const float* __restrict__ xb = x + (size_t)b * CHWn;
    const float* chan = xb + (size_t)am * HWn;

    // Lane k gathers window rows {k, k+4, k+8}.
    float nb = NEG_INF;
#pragma unroll
    for (int i = k; i < 9; i += 4) {
        const int rr = min(max(h - 4 + i, 0), Hn - 1);
        nb = fmaxf(nb, wrow_max(chan, rr, wa, lo, hi));
    }
    nb = fmaxf(nb, __shfl_xor_sync(0xFFFFFFFFu, nb, 1));
    nb = fmaxf(nb, __shfl_xor_sync(0xFFFFFFFFu, nb, 2));

    if (k == 0) {
        float res;
        if (cn == 1) {
            res = (nb <= mx) ? mx : 0.0f;   // nb >= mx always (center included)
        } else {
            // Exact tie path (statistically ~0 pixels): every channel equal to
            // the max contributes mx if it is also its own 9x9 local max.
            const float* xp = xb + h * Wn + w;
            int cnt = 0;
            for (int c = 0; c < Cn; ++c) {
                const float v = __ldg(xp + (size_t)c * HWn);
                if (v == mx) {
                    const float* ch2 = xb + (size_t)c * HWn;
                    float wb = NEG_INF;
                    for (int i = 0; i < 9; ++i) {
                        const int rr = min(max(h - 4 + i, 0), Hn - 1);
                        wb = fmaxf(wb, wrow_max(ch2, rr, wa, lo, hi));
                    }
                    if (wb <= mx) cnt++;
                }
            }
            res = mx * (float)cnt;
        }
        out[p] = res;
    }
}

extern "C" void kernel_launch(void* const* d_in, const int* in_sizes, int n_in,
                              void* d_out, int out_size) {
    const float* x = (const float*)d_in[0];
    float* out = (float*)d_out;
    (void)in_sizes; (void)n_in; (void)out_size;

    phaseA_kernel<<<(CHUNKS * NGRP) / 256, 256>>>(x);    // 1000 blocks
    phaseB_kernel<<<(4 * NPIX) / 256, 256>>>(x, out);    // 4000 blocks
}